// round 1
// baseline (speedup 1.0000x reference)
#include <cuda_runtime.h>
#include <stdint.h>

// Input order (metadata.txt): queries f32 (4,512,256), keys f32 (4,512,256),
// values f32 (4,512,256), Wq f32 (256,256), Wk f32 (256,256), wv f32 (256),
// valid_lens i32 (4).  Output: f32 (4,512,256).

#define NEG_MASK (-1.0e6f)

constexpr int B_ = 4, Q_ = 512, K_ = 512, D_ = 256, H_ = 256;

// Scratch (no allocations allowed -> __device__ globals)
__device__ float g_qproj[B_ * Q_ * H_];       // 2 MB
__device__ float g_kproj[B_ * K_ * H_];       // 2 MB
__device__ float g_scores[B_ * Q_ * K_];      // 4 MB (scores, then probs in-place)

__device__ __forceinline__ float tanh_fast(float x) {
    float y;
    asm("tanh.approx.f32 %0, %1;" : "=f"(y) : "f"(x));
    return y;
}

// ---------------------------------------------------------------------------
// Generic tiled FP32 GEMM: C = A(M x Kd) * B(Kd x N), row-major, batched via z.
// BM=BN=64, BK=16, 256 threads, 4x4 register tile per thread.
// ---------------------------------------------------------------------------
__global__ __launch_bounds__(256) void gemm_kernel(
    const float* __restrict__ A, const float* __restrict__ Bm,
    float* __restrict__ C, int M, int N, int Kd,
    long sA, long sB, long sC)
{
    constexpr int BM = 64, BN = 64, BK = 16;
    __shared__ float As[BK][BM + 4];   // +4 keeps 16B alignment for float4 reads
    __shared__ float Bs[BK][BN];

    const int bz = blockIdx.z;
    A  += (long)bz * sA;
    Bm += (long)bz * sB;
    C  += (long)bz * sC;

    const int t  = threadIdx.x;
    const int tx = t & 15;     // n direction
    const int ty = t >> 4;     // m direction
    const int m0 = blockIdx.y * BM;
    const int n0 = blockIdx.x * BN;

    float acc[4][4] = {};

    for (int k0 = 0; k0 < Kd; k0 += BK) {
        {   // A tile: 64x16, one float4 per thread, stored transposed
            int r  = t >> 2;
            int c4 = (t & 3) << 2;
            float4 v = *(const float4*)(A + (long)(m0 + r) * Kd + k0 + c4);
            As[c4 + 0][r] = v.x; As[c4 + 1][r] = v.y;
            As[c4 + 2][r] = v.z; As[c4 + 3][r] = v.w;
        }
        {   // B tile: 16x64, one float4 per thread
            int r  = t >> 4;
            int c4 = (t & 15) << 2;
            *(float4*)(&Bs[r][c4]) =
                *(const float4*)(Bm + (long)(k0 + r) * N + n0 + c4);
        }
        __syncthreads();

        #pragma unroll
        for (int kk = 0; kk < BK; kk++) {
            float4 a4 = *(const float4*)(&As[kk][ty << 2]);
            float4 b4 = *(const float4*)(&Bs[kk][tx << 2]);
            float a[4] = {a4.x, a4.y, a4.z, a4.w};
            float b[4] = {b4.x, b4.y, b4.z, b4.w};
            #pragma unroll
            for (int i = 0; i < 4; i++)
                #pragma unroll
                for (int j = 0; j < 4; j++)
                    acc[i][j] += a[i] * b[j];
        }
        __syncthreads();
    }

    #pragma unroll
    for (int i = 0; i < 4; i++) {
        float4 v = make_float4(acc[i][0], acc[i][1], acc[i][2], acc[i][3]);
        *(float4*)(C + (long)(m0 + (ty << 2) + i) * N + n0 + (tx << 2)) = v;
    }
}

// ---------------------------------------------------------------------------
// scores[b,q,k] = sum_h wv[h] * tanh(qproj[b,q,h] + kproj[b,k,h]), masked.
// Tile: 32 q x 64 k per block, 256 threads, each thread 2x4 (q,k) pairs.
// h processed in chunks of 32 through smem. Fully-masked k-tiles exit early.
// ---------------------------------------------------------------------------
__global__ __launch_bounds__(256) void scores_kernel(
    const float* __restrict__ wv, const int* __restrict__ valid)
{
    constexpr int TQ = 32, TK = 64, HC = 32;
    __shared__ float qs[TQ][HC + 1];
    __shared__ float ks[TK][HC + 1];
    __shared__ float wvs[H_];

    const int b  = blockIdx.z;
    const int q0 = blockIdx.y * TQ;
    const int k0 = blockIdx.x * TK;
    const int L  = valid[b];
    const int t  = threadIdx.x;
    const int tx = t & 15;    // k group of 4
    const int ty = t >> 4;    // q group of 2

    float* srow = g_scores + ((long)b * Q_ + q0) * K_ + k0;

    if (k0 >= L) {  // entire tile masked: skip all compute
        #pragma unroll
        for (int i = 0; i < 2; i++)
            #pragma unroll
            for (int j = 0; j < 4; j++)
                srow[(long)(ty * 2 + i) * K_ + tx * 4 + j] = NEG_MASK;
        return;
    }

    wvs[t] = wv[t];  // H_ == blockDim == 256

    const float* qp = g_qproj + ((long)b * Q_ + q0) * H_;
    const float* kp = g_kproj + ((long)b * K_ + k0) * H_;

    float acc[2][4] = {};

    for (int hc = 0; hc < H_; hc += HC) {
        {   // q tile: 32x32 floats, one float4 per thread
            int r  = t >> 3;
            int c4 = (t & 7) << 2;
            float4 v = *(const float4*)(qp + (long)r * H_ + hc + c4);
            qs[r][c4 + 0] = v.x; qs[r][c4 + 1] = v.y;
            qs[r][c4 + 2] = v.z; qs[r][c4 + 3] = v.w;
        }
        #pragma unroll
        for (int it = 0; it < 2; it++) {  // k tile: 64x32 floats
            int r  = (t >> 3) + it * 32;
            int c4 = (t & 7) << 2;
            float4 v = *(const float4*)(kp + (long)r * H_ + hc + c4);
            ks[r][c4 + 0] = v.x; ks[r][c4 + 1] = v.y;
            ks[r][c4 + 2] = v.z; ks[r][c4 + 3] = v.w;
        }
        __syncthreads();

        #pragma unroll 8
        for (int h = 0; h < HC; h++) {
            float w   = wvs[hc + h];
            float qv0 = qs[ty * 2 + 0][h];
            float qv1 = qs[ty * 2 + 1][h];
            float kv0 = ks[tx * 4 + 0][h];
            float kv1 = ks[tx * 4 + 1][h];
            float kv2 = ks[tx * 4 + 2][h];
            float kv3 = ks[tx * 4 + 3][h];
            acc[0][0] += w * tanh_fast(qv0 + kv0);
            acc[0][1] += w * tanh_fast(qv0 + kv1);
            acc[0][2] += w * tanh_fast(qv0 + kv2);
            acc[0][3] += w * tanh_fast(qv0 + kv3);
            acc[1][0] += w * tanh_fast(qv1 + kv0);
            acc[1][1] += w * tanh_fast(qv1 + kv1);
            acc[1][2] += w * tanh_fast(qv1 + kv2);
            acc[1][3] += w * tanh_fast(qv1 + kv3);
        }
        __syncthreads();
    }

    #pragma unroll
    for (int i = 0; i < 2; i++)
        #pragma unroll
        for (int j = 0; j < 4; j++) {
            int kk = tx * 4 + j;
            srow[(long)(ty * 2 + i) * K_ + kk] =
                (k0 + kk < L) ? acc[i][j] : NEG_MASK;
        }
}

// ---------------------------------------------------------------------------
// Masked softmax over K, in-place on g_scores (becomes probabilities).
// One block per (b, q) row; masked entries become exact 0 (matches -1e6 path:
// exp(-1e6 - max) underflows to 0 in fp32).
// ---------------------------------------------------------------------------
__global__ __launch_bounds__(256) void softmax_kernel(const int* __restrict__ valid)
{
    const int b = blockIdx.y;
    const int q = blockIdx.x;
    const int L = valid[b];
    const int t = threadIdx.x;
    float* row = g_scores + ((long)b * Q_ + q) * K_;

    __shared__ float red[256];

    float s0 = row[t];
    float s1 = row[t + 256];
    bool  v0 = (t < L);
    bool  v1 = (t + 256 < L);

    float m = fmaxf(v0 ? s0 : -INFINITY, v1 ? s1 : -INFINITY);
    red[t] = m;
    __syncthreads();
    for (int off = 128; off > 0; off >>= 1) {
        if (t < off) red[t] = fmaxf(red[t], red[t + off]);
        __syncthreads();
    }
    m = red[0];
    __syncthreads();

    float e0 = v0 ? __expf(s0 - m) : 0.0f;
    float e1 = v1 ? __expf(s1 - m) : 0.0f;
    red[t] = e0 + e1;
    __syncthreads();
    for (int off = 128; off > 0; off >>= 1) {
        if (t < off) red[t] += red[t + off];
        __syncthreads();
    }
    float inv = 1.0f / red[0];

    row[t]       = e0 * inv;
    row[t + 256] = e1 * inv;
}

// ---------------------------------------------------------------------------
extern "C" void kernel_launch(void* const* d_in, const int* in_sizes, int n_in,
                              void* d_out, int out_size)
{
    const float* queries = (const float*)d_in[0];
    const float* keys    = (const float*)d_in[1];
    const float* values  = (const float*)d_in[2];
    const float* Wq      = (const float*)d_in[3];
    const float* Wk      = (const float*)d_in[4];
    const float* wv      = (const float*)d_in[5];
    const int*   valid   = (const int*)d_in[6];
    float* out = (float*)d_out;
    (void)in_sizes; (void)n_in; (void)out_size;

    float *qproj, *kproj, *scores;
    cudaGetSymbolAddress((void**)&qproj,  g_qproj);
    cudaGetSymbolAddress((void**)&kproj,  g_kproj);
    cudaGetSymbolAddress((void**)&scores, g_scores);

    // 1) projections: (B*Q, D) @ (D, H)
    gemm_kernel<<<dim3(H_ / 64, (B_ * Q_) / 64, 1), 256>>>(
        queries, Wq, qproj, B_ * Q_, H_, D_, 0, 0, 0);
    gemm_kernel<<<dim3(H_ / 64, (B_ * K_) / 64, 1), 256>>>(
        keys, Wk, kproj, B_ * K_, H_, D_, 0, 0, 0);

    // 2) fused additive-attention scores (tanh over h), masked
    scores_kernel<<<dim3(K_ / 64, Q_ / 32, B_), 256>>>(wv, valid);

    // 3) masked softmax in-place -> probabilities
    softmax_kernel<<<dim3(Q_, B_), 256>>>(valid);

    // 4) out = probs @ values, batched over B
    gemm_kernel<<<dim3(D_ / 64, Q_ / 64, B_), 256>>>(
        scores, values, out, Q_, D_, K_,
        (long)Q_ * K_, (long)K_ * D_, (long)Q_ * D_);
}

// round 3
// speedup vs baseline: 1.1609x; 1.1609x over previous
#include <cuda_runtime.h>
#include <stdint.h>

// Inputs: queries f32 (4,512,256), keys f32 (4,512,256), values f32 (4,512,256),
// Wq f32 (256,256), Wk f32 (256,256), wv f32 (256), valid_lens i32 (4).
// Output: f32 (4,512,256).

constexpr int B_ = 4, Q_ = 512, K_ = 512, D_ = 256, H_ = 256;

__device__ float g_qproj[B_ * Q_ * H_];       // 2 MB
__device__ float g_kproj[B_ * K_ * H_];       // 2 MB
__device__ float g_scores[B_ * Q_ * K_];      // 4 MB (scores -> probs in-place)

__device__ __forceinline__ float tanh_fast(float x) {
    float y;
    asm("tanh.approx.f32 %0, %1;" : "=f"(y) : "f"(x));
    return y;
}

// ---------------------------------------------------------------------------
// Both projections in ONE launch: z=0 -> qproj = queries@Wq, z=1 -> kproj = keys@Wk
// M=2048, N=256, Kd=256. BM=BN=64, BK=16, 256 thr, 4x4 per thread. 256 blocks.
// ---------------------------------------------------------------------------
__global__ __launch_bounds__(256) void proj_kernel(
    const float* __restrict__ Qin, const float* __restrict__ Kin,
    const float* __restrict__ Wq,  const float* __restrict__ Wk)
{
    constexpr int BM = 64, BN = 64, BK = 16;
    __shared__ float As[BK][BM + 4];
    __shared__ float Bs[BK][BN];

    const float* A  = blockIdx.z ? Kin : Qin;
    const float* Bm = blockIdx.z ? Wk  : Wq;
    float*       C  = blockIdx.z ? g_kproj : g_qproj;

    const int t  = threadIdx.x;
    const int tx = t & 15;
    const int ty = t >> 4;
    const int m0 = blockIdx.y * BM;
    const int n0 = blockIdx.x * BN;

    float acc[4][4] = {};

    for (int k0 = 0; k0 < D_; k0 += BK) {
        {   int r  = t >> 2;
            int c4 = (t & 3) << 2;
            float4 v = *(const float4*)(A + (long)(m0 + r) * D_ + k0 + c4);
            As[c4 + 0][r] = v.x; As[c4 + 1][r] = v.y;
            As[c4 + 2][r] = v.z; As[c4 + 3][r] = v.w;
        }
        {   int r  = t >> 4;
            int c4 = (t & 15) << 2;
            *(float4*)(&Bs[r][c4]) =
                *(const float4*)(Bm + (long)(k0 + r) * H_ + n0 + c4);
        }
        __syncthreads();

        #pragma unroll
        for (int kk = 0; kk < BK; kk++) {
            float4 a4 = *(const float4*)(&As[kk][ty << 2]);
            float4 b4 = *(const float4*)(&Bs[kk][tx << 2]);
            float a[4] = {a4.x, a4.y, a4.z, a4.w};
            float b[4] = {b4.x, b4.y, b4.z, b4.w};
            #pragma unroll
            for (int i = 0; i < 4; i++)
                #pragma unroll
                for (int j = 0; j < 4; j++)
                    acc[i][j] += a[i] * b[j];
        }
        __syncthreads();
    }

    #pragma unroll
    for (int i = 0; i < 4; i++) {
        float4 v = make_float4(acc[i][0], acc[i][1], acc[i][2], acc[i][3]);
        *(float4*)(C + (long)(m0 + (ty << 2) + i) * H_ + n0 + (tx << 2)) = v;
    }
}

// ---------------------------------------------------------------------------
// scores[b,q,k] = sum_h wv[h] * tanh(qproj[b,q,h] + kproj[b,k,h]).
// Tile 32q x 64k, 256 thr, 2x4 per thread, h chunks of 32 via smem.
// Fully-masked k-tiles return immediately; no masked writes (softmax only
// reads k < L and rewrites all 512 entries).
// ---------------------------------------------------------------------------
__global__ __launch_bounds__(256) void scores_kernel(
    const float* __restrict__ wv, const int* __restrict__ valid)
{
    constexpr int TQ = 32, TK = 64, HC = 32;
    __shared__ float qs[TQ][HC + 1];
    __shared__ float ks[TK][HC + 1];
    __shared__ float wvs[H_];

    const int b  = blockIdx.z;
    const int q0 = blockIdx.y * TQ;
    const int k0 = blockIdx.x * TK;
    const int L  = valid[b];
    if (k0 >= L) return;

    const int t  = threadIdx.x;
    const int tx = t & 15;
    const int ty = t >> 4;

    wvs[t] = wv[t];

    const float* qp = g_qproj + ((long)b * Q_ + q0) * H_;
    const float* kp = g_kproj + ((long)b * K_ + k0) * H_;

    float acc[2][4] = {};

    for (int hc = 0; hc < H_; hc += HC) {
        {   int r  = t >> 3;
            int c4 = (t & 7) << 2;
            float4 v = *(const float4*)(qp + (long)r * H_ + hc + c4);
            qs[r][c4 + 0] = v.x; qs[r][c4 + 1] = v.y;
            qs[r][c4 + 2] = v.z; qs[r][c4 + 3] = v.w;
        }
        #pragma unroll
        for (int it = 0; it < 2; it++) {
            int r  = (t >> 3) + it * 32;
            int c4 = (t & 7) << 2;
            float4 v = *(const float4*)(kp + (long)r * H_ + hc + c4);
            ks[r][c4 + 0] = v.x; ks[r][c4 + 1] = v.y;
            ks[r][c4 + 2] = v.z; ks[r][c4 + 3] = v.w;
        }
        __syncthreads();

        #pragma unroll 8
        for (int h = 0; h < HC; h++) {
            float w   = wvs[hc + h];
            float qv0 = qs[ty * 2 + 0][h];
            float qv1 = qs[ty * 2 + 1][h];
            float kv0 = ks[tx * 4 + 0][h];
            float kv1 = ks[tx * 4 + 1][h];
            float kv2 = ks[tx * 4 + 2][h];
            float kv3 = ks[tx * 4 + 3][h];
            acc[0][0] += w * tanh_fast(qv0 + kv0);
            acc[0][1] += w * tanh_fast(qv0 + kv1);
            acc[0][2] += w * tanh_fast(qv0 + kv2);
            acc[0][3] += w * tanh_fast(qv0 + kv3);
            acc[1][0] += w * tanh_fast(qv1 + kv0);
            acc[1][1] += w * tanh_fast(qv1 + kv1);
            acc[1][2] += w * tanh_fast(qv1 + kv2);
            acc[1][3] += w * tanh_fast(qv1 + kv3);
        }
        __syncthreads();
    }

    float* srow = g_scores + ((long)b * Q_ + q0) * K_ + k0;
    #pragma unroll
    for (int i = 0; i < 2; i++) {
        float4 v = make_float4(acc[i][0], acc[i][1], acc[i][2], acc[i][3]);
        *(float4*)(srow + (long)(ty * 2 + i) * K_ + tx * 4) = v;
    }
}

// ---------------------------------------------------------------------------
// Warp-per-row masked softmax, in-place. 8 rows per 256-thread block, pure
// shuffle reductions, no __syncthreads. Writes exact 0 for k >= L.
// ---------------------------------------------------------------------------
__global__ __launch_bounds__(256) void softmax_kernel(const int* __restrict__ valid)
{
    const int warp = threadIdx.x >> 5;
    const int lane = threadIdx.x & 31;
    const int row  = blockIdx.x * 8 + warp;          // [0, B_*Q_)
    const int b    = row >> 9;                        // row / Q_
    const int L    = valid[b];
    float* p = g_scores + (long)row * K_;

    float s[16];
    float m = -INFINITY;
    #pragma unroll
    for (int i = 0; i < 16; i++) {
        int idx = lane + (i << 5);
        s[i] = (idx < L) ? p[idx] : -INFINITY;
        m = fmaxf(m, s[i]);
    }
    #pragma unroll
    for (int o = 16; o; o >>= 1) m = fmaxf(m, __shfl_xor_sync(0xffffffffu, m, o));

    float sum = 0.0f;
    #pragma unroll
    for (int i = 0; i < 16; i++) {
        s[i] = (s[i] == -INFINITY) ? 0.0f : __expf(s[i] - m);
        sum += s[i];
    }
    #pragma unroll
    for (int o = 16; o; o >>= 1) sum += __shfl_xor_sync(0xffffffffu, sum, o);
    const float inv = 1.0f / sum;

    #pragma unroll
    for (int i = 0; i < 16; i++) p[lane + (i << 5)] = s[i] * inv;
}

// ---------------------------------------------------------------------------
// out[b] = probs[b] @ values[b]; skips k-tiles entirely beyond valid_len
// (probs there are exact zeros). BM=64, BN=32 -> 256 blocks.
// ---------------------------------------------------------------------------
__global__ __launch_bounds__(256) void av_kernel(
    const float* __restrict__ V, const int* __restrict__ valid,
    float* __restrict__ out)
{
    constexpr int BM = 64, BN = 32, BK = 16;
    __shared__ float Ps[BK][BM + 4];
    __shared__ float Vs[BK][BN];

    const int b = blockIdx.z;
    const int L = valid[b];
    const float* P  = g_scores + (long)b * Q_ * K_;
    const float* Vb = V + (long)b * K_ * D_;
    float*       C  = out + (long)b * Q_ * D_;

    const int t  = threadIdx.x;
    const int tx = t & 15;
    const int ty = t >> 4;
    const int m0 = blockIdx.y * BM;
    const int n0 = blockIdx.x * BN;

    float acc[4][2] = {};

    for (int k0 = 0; k0 < L; k0 += BK) {
        {   int r  = t >> 2;
            int c4 = (t & 3) << 2;
            float4 v = *(const float4*)(P + (long)(m0 + r) * K_ + k0 + c4);
            Ps[c4 + 0][r] = v.x; Ps[c4 + 1][r] = v.y;
            Ps[c4 + 2][r] = v.z; Ps[c4 + 3][r] = v.w;
        }
        if (t < 128) {
            int r  = t >> 3;
            int c4 = (t & 7) << 2;
            *(float4*)(&Vs[r][c4]) =
                *(const float4*)(Vb + (long)(k0 + r) * D_ + n0 + c4);
        }
        __syncthreads();

        #pragma unroll
        for (int kk = 0; kk < BK; kk++) {
            float4 a4 = *(const float4*)(&Ps[kk][ty << 2]);
            float2 b2 = *(const float2*)(&Vs[kk][tx << 1]);
            acc[0][0] += a4.x * b2.x; acc[0][1] += a4.x * b2.y;
            acc[1][0] += a4.y * b2.x; acc[1][1] += a4.y * b2.y;
            acc[2][0] += a4.z * b2.x; acc[2][1] += a4.z * b2.y;
            acc[3][0] += a4.w * b2.x; acc[3][1] += a4.w * b2.y;
        }
        __syncthreads();
    }

    #pragma unroll
    for (int i = 0; i < 4; i++) {
        float2 v = make_float2(acc[i][0], acc[i][1]);
        *(float2*)(C + (long)(m0 + (ty << 2) + i) * D_ + n0 + (tx << 1)) = v;
    }
}

// ---------------------------------------------------------------------------
extern "C" void kernel_launch(void* const* d_in, const int* in_sizes, int n_in,
                              void* d_out, int out_size)
{
    const float* queries = (const float*)d_in[0];
    const float* keys    = (const float*)d_in[1];
    const float* values  = (const float*)d_in[2];
    const float* Wq      = (const float*)d_in[3];
    const float* Wk      = (const float*)d_in[4];
    const float* wv      = (const float*)d_in[5];
    const int*   valid   = (const int*)d_in[6];
    float* out = (float*)d_out;
    (void)in_sizes; (void)n_in; (void)out_size;

    // 1) both projections, one launch (256 blocks)
    proj_kernel<<<dim3(H_ / 64, (B_ * Q_) / 64, 2), 256>>>(queries, keys, Wq, Wk);

    // 2) fused additive-attention scores (tanh over h), masked tiles skipped
    scores_kernel<<<dim3(K_ / 64, Q_ / 32, B_), 256>>>(wv, valid);

    // 3) warp-per-row masked softmax -> probabilities (zeros beyond L)
    softmax_kernel<<<dim3((B_ * Q_) / 8), 256>>>(valid);

    // 4) out = probs @ values, masked k-tiles skipped (256 blocks)
    av_kernel<<<dim3(D_ / 32, Q_ / 64, B_), 256>>>(values, valid, out);
}